// round 11
// baseline (speedup 1.0000x reference)
#include <cuda_runtime.h>

#define N_ATOMS 1024
#define NIMG 27
#define TPB 256                           // threads per block = pairs per tile
#define TILE_FLOATS (TPB * NIMG)          // 6912
#define TILE_F4 (TILE_FLOATS / 4)         // 1728 = 6*256 + 192
#define TILES_PER_BLOCK 4
#define GRID_BLOCKS (N_ATOMS * N_ATOMS / TPB / TILES_PER_BLOCK)   // 1024

// ---------------------------------------------------------------------------
// Single-wave direct-STG kernel. The chip-level LTS store cap (~6300 B/cyc,
// path-independent: STG == TMA) makes ~16.4us the floor for the 113MB write;
// R6 (STG, 4096 CTAs) ran at 93% of it. This variant removes the remaining
// scheduling loss: 1024 CTAs x 256 thr at occ 8 -> EVERY CTA resident in one
// wave (1024 <= 148*8), no wave transitions, no partial-wave tail. Each block
// builds 4 output tiles directly in GMEM: zero-stream 7 STG.128/thread, one
// __syncthreads (hit addresses interleave into peers' zero float4 ranges),
// then scatter the rare edge. Tiles are distinct GMEM ranges -> no cross-tile
// hazard, no extra syncs.
//
// Screen (validated R4/R6/R7/R10, rel_err 4.76e-8): the unique candidate
// image is o* = -rint(frac_j - frac_i); |w| < 5 forces |dfrac|_inf ~< 0.175
// < 0.5, and no two images can both satisfy |.|_inf < 0.5.
// ---------------------------------------------------------------------------
__global__ __launch_bounds__(TPB, 8)
void prg_wave_kernel(const float* __restrict__ frac,
                     const float* __restrict__ cell,
                     float* __restrict__ out) {
    const int tid = threadIdx.x;

    // cell: 9 uniform floats, loaded once per block (L1 broadcast)
    const float c00 = cell[0], c01 = cell[1], c02 = cell[2];
    const float c10 = cell[3], c11 = cell[4], c12 = cell[5];
    const float c20 = cell[6], c21 = cell[7], c22 = cell[8];

    #pragma unroll
    for (int t = 0; t < TILES_PER_BLOCK; t++) {
        const int tile_id = blockIdx.x * TILES_PER_BLOCK + t;
        const int pair = tile_id * TPB + tid;
        const int i = pair >> 10;
        const int j = pair & 1023;

        // Issue this tile's input loads before the zero stream; their ~600cyc
        // latency hides under the stores (and under other resident CTAs).
        const float fi0 = frac[i * 3 + 0], fi1 = frac[i * 3 + 1], fi2 = frac[i * 3 + 2];
        const float fj0 = frac[j * 3 + 0], fj1 = frac[j * 3 + 1], fj2 = frac[j * 3 + 2];

        // --- zero this tile: 1728 float4 over 256 threads (6 full + 192) ---
        float* tile_base = out + (size_t)tile_id * TILE_FLOATS;
        {
            float4* z4 = (float4*)tile_base;
            const float4 z = make_float4(0.f, 0.f, 0.f, 0.f);
            #pragma unroll
            for (int q = 0; q < 6; q++)
                z4[tid + q * TPB] = z;
            if (tid < TILE_F4 - 6 * TPB)           // tail: 192 threads
                z4[tid + 6 * TPB] = z;
        }

        // --- screen the unique candidate image (exact reference op order) ---
        const float t0 = fj0 - fi0, t1 = fj1 - fi1, t2 = fj2 - fi2;
        const float o0 = -rintf(t0), o1 = -rintf(t1), o2 = -rintf(t2);
        const float d0 = t0 + o0, d1 = t1 + o1, d2 = t2 + o2;

        const float wx = fmaf(d2, c20, fmaf(d1, c10, d0 * c00));
        const float wy = fmaf(d2, c21, fmaf(d1, c11, d0 * c01));
        const float wz = fmaf(d2, c22, fmaf(d1, c12, d0 * c02));
        const float e2 = fmaf(wz, wz, fmaf(wy, wy, wx * wx));

        // Zeros land before hits: a hit address lies inside a PEER thread's
        // zero float4 range (CTA scope suffices; tile is block-private).
        __syncthreads();

        if (e2 > 1e-12f && e2 < 25.002f) {
            const float dist = __fsqrt_rn(e2);
            if (dist < 5.0f) {
                const int k = ((int)o0 + 1) * 9 + ((int)o1 + 1) * 3 + ((int)o2 + 1);
                tile_base[tid * NIMG + k] = dist;
            }
        }
        // No trailing sync: next tile touches disjoint GMEM addresses.
    }
}

extern "C" void kernel_launch(void* const* d_in, const int* in_sizes, int n_in,
                              void* d_out, int out_size) {
    const float* frac = (const float*)d_in[0];  // [1024, 3]
    const float* cell = (const float*)d_in[1];  // [3, 3]
    float* out = (float*)d_out;                 // [1024, 1024, 27]

    prg_wave_kernel<<<GRID_BLOCKS, TPB>>>(frac, cell, out);
}

// round 12
// speedup vs baseline: 1.0977x; 1.0977x over previous
#include <cuda_runtime.h>

#define N_ATOMS 1024
#define NIMG 27
#define PPB 256                         // pairs per block (= threads)
#define TILE_FLOATS (PPB * NIMG)        // 6912
#define WARP_F4 216                     // floats per warp / 4 = 32*27/4 (exact)

// ---------------------------------------------------------------------------
// R6 structure (the 17.4us / 21.0us best) with warp-local ordering.
// The kernel is pinned at the chip-level LTS store cap (~6300 B/cyc,
// path-independent; R6..R11 all land 17.4-19.3us kernel). Remaining trim:
// a warp's 32 pairs own floats [32w*27, 32w*27+864) = 216 float4, exactly
// warp-aligned. Each warp zeroes its own 216 float4, so every hit address
// (tid*27+k) falls inside the hit thread's OWN warp's zero range ->
// __syncwarp() (no cross-warp BAR drain) suffices to order zeros before hits.
//
// Screen (validated R4/R6/R7/R10/R11, rel_err 4.76e-8): the unique candidate
// image is o* = -rint(frac_j - frac_i); |w| < 5 forces |dfrac|_inf ~< 0.175
// < 0.5, and no two distinct images can both satisfy |.|_inf < 0.5.
// ---------------------------------------------------------------------------
__global__ __launch_bounds__(PPB)
void prg_warp_kernel(const float* __restrict__ frac,
                     const float* __restrict__ cell,
                     float* __restrict__ out) {
    const int tid = threadIdx.x;
    const int lane = tid & 31;
    const int warp = tid >> 5;
    const int pair = blockIdx.x * PPB + tid;
    const int i = pair >> 10;
    const int j = pair & 1023;

    // Issue input loads first; ~600cyc latency hides under the zero stream.
    const float fi0 = frac[i * 3 + 0], fi1 = frac[i * 3 + 1], fi2 = frac[i * 3 + 2];
    const float fj0 = frac[j * 3 + 0], fj1 = frac[j * 3 + 1], fj2 = frac[j * 3 + 2];
    const float c00 = cell[0], c01 = cell[1], c02 = cell[2];
    const float c10 = cell[3], c11 = cell[4], c12 = cell[5];
    const float c20 = cell[6], c21 = cell[7], c22 = cell[8];

    float* tile_base = out + (size_t)blockIdx.x * TILE_FLOATS;

    // --- zero: each warp owns its 216 float4 (6 full rounds + 24-lane tail) ---
    {
        float4* w4 = (float4*)tile_base + warp * WARP_F4;
        const float4 z = make_float4(0.f, 0.f, 0.f, 0.f);
        #pragma unroll
        for (int q = 0; q < 6; q++)
            w4[lane + q * 32] = z;
        if (lane < WARP_F4 - 6 * 32)             // tail: 24 lanes
            w4[lane + 6 * 32] = z;
    }

    // --- screen the unique candidate image (exact reference op order) ---
    const float t0 = fj0 - fi0, t1 = fj1 - fi1, t2 = fj2 - fi2;
    const float o0 = -rintf(t0), o1 = -rintf(t1), o2 = -rintf(t2);
    const float d0 = t0 + o0, d1 = t1 + o1, d2 = t2 + o2;

    const float wx = fmaf(d2, c20, fmaf(d1, c10, d0 * c00));
    const float wy = fmaf(d2, c21, fmaf(d1, c11, d0 * c01));
    const float wz = fmaf(d2, c22, fmaf(d1, c12, d0 * c02));
    const float e2 = fmaf(wz, wz, fmaf(wy, wy, wx * wx));

    // Order this warp's zeros before this warp's hit stores. Hit addresses
    // never leave the warp's own 864-float range, so warp scope suffices.
    __syncwarp();

    if (e2 > 1e-12f && e2 < 25.002f) {
        const float dist = __fsqrt_rn(e2);
        if (dist < 5.0f) {
            const int k = ((int)o0 + 1) * 9 + ((int)o1 + 1) * 3 + ((int)o2 + 1);
            tile_base[tid * NIMG + k] = dist;
        }
    }
}

extern "C" void kernel_launch(void* const* d_in, const int* in_sizes, int n_in,
                              void* d_out, int out_size) {
    const float* frac = (const float*)d_in[0];  // [1024, 3]
    const float* cell = (const float*)d_in[1];  // [3, 3]
    float* out = (float*)d_out;                 // [1024, 1024, 27]

    const int n_pairs = N_ATOMS * N_ATOMS;
    prg_warp_kernel<<<n_pairs / PPB, PPB>>>(frac, cell, out);
}